// round 3
// baseline (speedup 1.0000x reference)
#include <cuda_runtime.h>
#include <cuda_bf16.h>
#include <cstdint>

#define DEVINL __device__ __forceinline__

// ---------------- problem constants ----------------
static constexpr int BATCH = 4;
static constexpr int NSEQ  = 4096;
static constexpr int DDIM  = 512;
// scale * log2(e): logits kept in log2 domain so epilogue is a bare ex2.approx
static constexpr float CLOG2E = 0.09016844005556021f;

// ---------------- tiling ----------------
static constexpr int MT    = 128;            // q rows per CTA
static constexpr int NTILE = 256;            // kv rows per accumulation tile
static constexpr int KTOT  = 1536;           // 3 precision terms * 512
static constexpr int KC    = 64;             // k per chunk (128B smem rows)
static constexpr int NCH   = KTOT / KC;      // 24 chunks per N-tile
static constexpr int NTC   = NSEQ / NTILE;   // 16 N-tiles
static constexpr int TOTAL = NTC * NCH;      // 384 pipeline iterations
static constexpr int STAGES = 3;

static constexpr int ABYTES = MT * KC * 2;       // 16384
static constexpr int BBYTES = NTILE * KC * 2;    // 32768
static constexpr int STB    = ABYTES + BBYTES;   // 49152
static constexpr int SMEM_TOTAL = 1024 + STAGES * STB + 512;  // align slack + rowacc

// ---------------- scratch (device globals: no allocs allowed) ----------------
// qcat rows: [qh*c | ql*c | qh*c], kcat rows: [kh | kh | kl]  (bf16, K=1536)
__device__ __align__(1024) __nv_bfloat16 g_qcat[(size_t)BATCH * NSEQ * KTOT];
__device__ __align__(1024) __nv_bfloat16 g_kcat[(size_t)BATCH * NSEQ * KTOT];
__device__ float g_diagexp[BATCH * NSEQ];

// ---------------- PTX helpers ----------------
DEVINL uint32_t smem_u32(const void* p) {
    uint32_t a;
    asm("{ .reg .u64 t; cvta.to.shared.u64 t, %1; cvt.u32.u64 %0, t; }"
        : "=r"(a) : "l"(p));
    return a;
}
DEVINL uint32_t sw128(uint32_t off) { return off ^ ((off >> 3) & 0x70); }

DEVINL void cp_async16(uint32_t dst, const void* src) {
    asm volatile("cp.async.cg.shared.global [%0], [%1], 16;"
                 :: "r"(dst), "l"(src) : "memory");
}
DEVINL void cp_commit() { asm volatile("cp.async.commit_group;" ::: "memory"); }
template <int N>
DEVINL void cp_wait_group() { asm volatile("cp.async.wait_group %0;" :: "n"(N) : "memory"); }

DEVINL void ldsm4(uint32_t (&r)[4], uint32_t addr) {
    asm volatile("ldmatrix.sync.aligned.m8n8.x4.shared.b16 {%0,%1,%2,%3}, [%4];"
                 : "=r"(r[0]), "=r"(r[1]), "=r"(r[2]), "=r"(r[3]) : "r"(addr));
}
DEVINL void mma16816(float* d, const uint32_t* a, uint32_t b0, uint32_t b1) {
    asm volatile(
        "mma.sync.aligned.m16n8k16.row.col.f32.bf16.bf16.f32 "
        "{%0,%1,%2,%3}, {%4,%5,%6,%7}, {%8,%9}, {%0,%1,%2,%3};"
        : "+f"(d[0]), "+f"(d[1]), "+f"(d[2]), "+f"(d[3])
        : "r"(a[0]), "r"(a[1]), "r"(a[2]), "r"(a[3]), "r"(b0), "r"(b1));
}
DEVINL float ex2(float x) {
    float y;
    asm("ex2.approx.ftz.f32 %0, %1;" : "=f"(y) : "f"(x));
    return y;
}

// ---------------- prep: fp32 -> bf16 hi/lo split, K=1536 concat layout ----------------
__global__ void __launch_bounds__(512) prep_kernel(const float* __restrict__ q,
                                                   const float* __restrict__ kv) {
    size_t idx = (size_t)blockIdx.x * 512 + threadIdx.x;  // float4 id (exact grid)
    size_t row = idx >> 7;                                // 128 float4 per 512-row
    int    dp  = (int)(idx & 127) << 2;

    {   // q scaled by CLOG2E, split into hi+lo, layout [hi | lo | hi]
        float4 a = reinterpret_cast<const float4*>(q)[idx];
        float sx = a.x * CLOG2E, sy = a.y * CLOG2E, sz = a.z * CLOG2E, sw = a.w * CLOG2E;
        __nv_bfloat16 hx = __float2bfloat16(sx), hy = __float2bfloat16(sy);
        __nv_bfloat16 hz = __float2bfloat16(sz), hw = __float2bfloat16(sw);
        __nv_bfloat16 lx = __float2bfloat16(sx - __bfloat162float(hx));
        __nv_bfloat16 ly = __float2bfloat16(sy - __bfloat162float(hy));
        __nv_bfloat16 lz = __float2bfloat16(sz - __bfloat162float(hz));
        __nv_bfloat16 lw = __float2bfloat16(sw - __bfloat162float(hw));
        __nv_bfloat162 h0 = __halves2bfloat162(hx, hy), h1 = __halves2bfloat162(hz, hw);
        __nv_bfloat162 l0 = __halves2bfloat162(lx, ly), l1 = __halves2bfloat162(lz, lw);
        __nv_bfloat16* base = g_qcat + row * KTOT + dp;
        reinterpret_cast<__nv_bfloat162*>(base)[0]        = h0;
        reinterpret_cast<__nv_bfloat162*>(base)[1]        = h1;
        reinterpret_cast<__nv_bfloat162*>(base + 512)[0]  = l0;
        reinterpret_cast<__nv_bfloat162*>(base + 512)[1]  = l1;
        reinterpret_cast<__nv_bfloat162*>(base + 1024)[0] = h0;
        reinterpret_cast<__nv_bfloat162*>(base + 1024)[1] = h1;
    }
    {   // kv unscaled, layout [hi | hi | lo]
        float4 a = reinterpret_cast<const float4*>(kv)[idx];
        __nv_bfloat16 hx = __float2bfloat16(a.x), hy = __float2bfloat16(a.y);
        __nv_bfloat16 hz = __float2bfloat16(a.z), hw = __float2bfloat16(a.w);
        __nv_bfloat16 lx = __float2bfloat16(a.x - __bfloat162float(hx));
        __nv_bfloat16 ly = __float2bfloat16(a.y - __bfloat162float(hy));
        __nv_bfloat16 lz = __float2bfloat16(a.z - __bfloat162float(hz));
        __nv_bfloat16 lw = __float2bfloat16(a.w - __bfloat162float(hw));
        __nv_bfloat162 h0 = __halves2bfloat162(hx, hy), h1 = __halves2bfloat162(hz, hw);
        __nv_bfloat162 l0 = __halves2bfloat162(lx, ly), l1 = __halves2bfloat162(lz, lw);
        __nv_bfloat16* base = g_kcat + row * KTOT + dp;
        reinterpret_cast<__nv_bfloat162*>(base)[0]        = h0;
        reinterpret_cast<__nv_bfloat162*>(base)[1]        = h1;
        reinterpret_cast<__nv_bfloat162*>(base + 512)[0]  = h0;
        reinterpret_cast<__nv_bfloat162*>(base + 512)[1]  = h1;
        reinterpret_cast<__nv_bfloat162*>(base + 1024)[0] = l0;
        reinterpret_cast<__nv_bfloat162*>(base + 1024)[1] = l1;
    }
}

// ---------------- exact fp32 diagonal: 2^(c * <q_n, kv_n>) ----------------
__global__ void __launch_bounds__(256) diag_kernel(const float* __restrict__ q,
                                                   const float* __restrict__ kv) {
    int row  = blockIdx.x * 8 + (threadIdx.x >> 5);
    int lane = threadIdx.x & 31;
    const float* qr = q  + (size_t)row * DDIM;
    const float* kr = kv + (size_t)row * DDIM;
    float s = 0.f;
#pragma unroll
    for (int i = 0; i < 16; ++i) s += qr[lane + 32 * i] * kr[lane + 32 * i];
#pragma unroll
    for (int off = 16; off; off >>= 1) s += __shfl_xor_sync(0xffffffffu, s, off);
    if (lane == 0) g_diagexp[row] = exp2f(CLOG2E * s);
}

// ---------------- main fused GEMM + normalizer kernel ----------------
__global__ void __launch_bounds__(256, 1) main_kernel(float* __restrict__ out) {
    extern __shared__ char smem_raw[];
    const uint32_t base = (smem_u32(smem_raw) + 1023u) & ~1023u;
    const uint32_t st0  = base;
    float* racc = reinterpret_cast<float*>(smem_raw +
                     ((base + STAGES * STB) - smem_u32(smem_raw)));

    const int tid  = threadIdx.x;
    const int wid  = tid >> 5;
    const int lane = tid & 31;
    const int bid  = blockIdx.x;

    if (tid < MT) racc[tid] = 0.f;

    // per-thread cp.async vector descriptors (16B vectors)
    int qoff[4]; uint32_t qdst[4];
#pragma unroll
    for (int i = 0; i < 4; ++i) {
        int v = tid + i * 256, r = v >> 3, j = v & 7;
        qoff[i] = r * KTOT + j * 8;
        qdst[i] = sw128((uint32_t)(r * 128 + j * 16));
    }
    int koff[8]; uint32_t kdst[8];
#pragma unroll
    for (int i = 0; i < 8; ++i) {
        int v = tid + i * 256, r = v >> 3, j = v & 7;
        koff[i] = r * KTOT + j * 8;
        kdst[i] = sw128((uint32_t)(r * 128 + j * 16));
    }

    const __nv_bfloat16* qg = g_qcat + (size_t)bid * MT * KTOT;
    const __nv_bfloat16* kg = g_kcat + (size_t)(bid >> 5) * NSEQ * KTOT;

    auto issue = [&](int it) {
        const int nt = it / NCH, c = it - nt * NCH;
        const uint32_t sA = st0 + (it % STAGES) * STB;
        const uint32_t sB = sA + ABYTES;
        const __nv_bfloat16* qs = qg + c * KC;
#pragma unroll
        for (int i = 0; i < 4; ++i) cp_async16(sA + qdst[i], qs + qoff[i]);
        const __nv_bfloat16* ks = kg + (size_t)nt * NTILE * KTOT + c * KC;
#pragma unroll
        for (int i = 0; i < 8; ++i) cp_async16(sB + kdst[i], ks + koff[i]);
        cp_commit();
    };

    // warp tile: 2 M-warps x 4 N-warps, each 64x64
    const int m0 = (wid & 1) * 64;
    const int n0 = (wid >> 1) * 64;
    const int lr = lane & 15;          // ldmatrix row within 16
    const int lcb = (lane >> 4) * 16;  // ldmatrix 16B column group

    uint32_t aBase[4], aSw[4], bBase[4], bSw[4];
#pragma unroll
    for (int f = 0; f < 4; ++f) {
        int ra = m0 + f * 16 + lr;
        aBase[f] = (uint32_t)(ra * 128); aSw[f] = (uint32_t)((ra & 7) << 4);
        int rb = n0 + f * 16 + lr;
        bBase[f] = (uint32_t)(rb * 128); bSw[f] = (uint32_t)((rb & 7) << 4);
    }

    float c[4][8][4];
#pragma unroll
    for (int mf = 0; mf < 4; ++mf)
#pragma unroll
        for (int nf = 0; nf < 8; ++nf)
#pragma unroll
            for (int k = 0; k < 4; ++k) c[mf][nf][k] = 0.f;

    issue(0);
    issue(1);

    for (int it = 0; it < TOTAL; ++it) {
        if (it + 2 < TOTAL) { issue(it + 2); cp_wait_group<2>(); }
        else if (it + 1 < TOTAL) cp_wait_group<1>();
        else cp_wait_group<0>();
        __syncthreads();

        const uint32_t sA = st0 + (it % STAGES) * STB;
        const uint32_t sB = sA + ABYTES;

#pragma unroll
        for (int kk = 0; kk < 4; ++kk) {
            const uint32_t cb = (uint32_t)(kk * 32) + lcb;
            uint32_t a[4][4], b[4][4];
#pragma unroll
            for (int f = 0; f < 4; ++f) ldsm4(a[f], sA + aBase[f] + (cb ^ aSw[f]));
#pragma unroll
            for (int f = 0; f < 4; ++f) ldsm4(b[f], sB + bBase[f] + (cb ^ bSw[f]));
#pragma unroll
            for (int mf = 0; mf < 4; ++mf)
#pragma unroll
                for (int g = 0; g < 4; ++g) {
                    mma16816(c[mf][2 * g],     a[mf], b[g][0], b[g][2]);
                    mma16816(c[mf][2 * g + 1], a[mf], b[g][1], b[g][3]);
                }
        }

        if (it % NCH == NCH - 1) {
            // epilogue for this 256-col kv tile: rowsum of 2^score
#pragma unroll
            for (int mf = 0; mf < 4; ++mf) {
                float s0 = 0.f, s1 = 0.f;
#pragma unroll
                for (int nf = 0; nf < 8; ++nf) {
                    s0 += ex2(c[mf][nf][0]) + ex2(c[mf][nf][1]);
                    s1 += ex2(c[mf][nf][2]) + ex2(c[mf][nf][3]);
                    c[mf][nf][0] = 0.f; c[mf][nf][1] = 0.f;
                    c[mf][nf][2] = 0.f; c[mf][nf][3] = 0.f;
                }
                s0 += __shfl_xor_sync(0xffffffffu, s0, 1);
                s0 += __shfl_xor_sync(0xffffffffu, s0, 2);
                s1 += __shfl_xor_sync(0xffffffffu, s1, 1);
                s1 += __shfl_xor_sync(0xffffffffu, s1, 2);
                if ((lane & 3) == 0) {
                    atomicAdd(&racc[m0 + mf * 16 + (lane >> 2)], s0);
                    atomicAdd(&racc[m0 + mf * 16 + 8 + (lane >> 2)], s1);
                }
            }
        }
        __syncthreads();
    }

    if (tid < MT) {
        const int row = bid * MT + tid;
        out[row] = g_diagexp[row] / racc[tid];
    }
}

extern "C" void kernel_launch(void* const* d_in, const int* in_sizes, int n_in,
                              void* d_out, int out_size) {
    const float* q  = (const float*)d_in[0];
    const float* kv = (const float*)d_in[1];
    float* out = (float*)d_out;

    prep_kernel<<<4096, 512>>>(q, kv);
    diag_kernel<<<2048, 256>>>(q, kv);

    cudaFuncSetAttribute(main_kernel, cudaFuncAttributeMaxDynamicSharedMemorySize,
                         SMEM_TOTAL);
    main_kernel<<<BATCH * (NSEQ / MT), 256, SMEM_TOTAL>>>(out);
}

// round 4
// speedup vs baseline: 1.0387x; 1.0387x over previous
#include <cuda_runtime.h>
#include <cuda_bf16.h>
#include <cstdint>

#define DEVINL __device__ __forceinline__

// ---------------- problem constants ----------------
static constexpr int BATCH = 4;
static constexpr int NSEQ  = 4096;
static constexpr int DDIM  = 512;
// scale * log2(e): logits kept in log2 domain so epilogue is a bare ex2.approx
static constexpr float CLOG2E = 0.09016844005556021f;

// ---------------- tiling ----------------
static constexpr int MT    = 128;            // q rows per CTA
static constexpr int NTILE = 256;            // kv rows per accumulation tile
static constexpr int KSTORE = 1024;          // stored K per row: [hi(512) | lo(512)]
static constexpr int KC    = 64;             // k per chunk (128B smem rows)
static constexpr int NCH   = 24;             // 3 terms * (512/64) chunks per N-tile
static constexpr int NTC   = NSEQ / NTILE;   // 16 N-tiles
static constexpr int TOTAL = NTC * NCH;      // 384 pipeline iterations
static constexpr int STAGES = 4;

static constexpr int ABYTES = MT * KC * 2;       // 16384
static constexpr int BBYTES = NTILE * KC * 2;    // 32768
static constexpr int STB    = ABYTES + BBYTES;   // 49152
static constexpr int SMEM_TOTAL = 1024 + STAGES * STB + 512;  // slack + racc

// ---------------- scratch (device globals: no allocs allowed) ----------------
// qcat rows: [qh*c | ql*c], kcat rows: [kh | kl]   (bf16, K=1024 stored)
__device__ __align__(1024) __nv_bfloat16 g_qcat[(size_t)BATCH * NSEQ * KSTORE];
__device__ __align__(1024) __nv_bfloat16 g_kcat[(size_t)BATCH * NSEQ * KSTORE];
__device__ float g_diagexp[BATCH * NSEQ];

// ---------------- PTX helpers ----------------
DEVINL uint32_t smem_u32(const void* p) {
    uint32_t a;
    asm("{ .reg .u64 t; cvta.to.shared.u64 t, %1; cvt.u32.u64 %0, t; }"
        : "=r"(a) : "l"(p));
    return a;
}
DEVINL uint32_t sw128(uint32_t off) { return off ^ ((off >> 3) & 0x70); }

DEVINL void cp_async16(uint32_t dst, const void* src) {
    asm volatile("cp.async.cg.shared.global [%0], [%1], 16;"
                 :: "r"(dst), "l"(src) : "memory");
}
DEVINL void cp_commit() { asm volatile("cp.async.commit_group;" ::: "memory"); }
template <int N>
DEVINL void cp_wait_group() { asm volatile("cp.async.wait_group %0;" :: "n"(N) : "memory"); }

DEVINL void ldsm4(uint32_t (&r)[4], uint32_t addr) {
    asm volatile("ldmatrix.sync.aligned.m8n8.x4.shared.b16 {%0,%1,%2,%3}, [%4];"
                 : "=r"(r[0]), "=r"(r[1]), "=r"(r[2]), "=r"(r[3]) : "r"(addr));
}
DEVINL void mma16816(float* d, const uint32_t* a, uint32_t b0, uint32_t b1) {
    asm volatile(
        "mma.sync.aligned.m16n8k16.row.col.f32.bf16.bf16.f32 "
        "{%0,%1,%2,%3}, {%4,%5,%6,%7}, {%8,%9}, {%0,%1,%2,%3};"
        : "+f"(d[0]), "+f"(d[1]), "+f"(d[2]), "+f"(d[3])
        : "r"(a[0]), "r"(a[1]), "r"(a[2]), "r"(a[3]), "r"(b0), "r"(b1));
}
DEVINL float ex2(float x) {
    float y;
    asm("ex2.approx.ftz.f32 %0, %1;" : "=f"(y) : "f"(x));
    return y;
}

// ---------------- prep: fp32 -> bf16 hi/lo split, K=1024 [hi|lo] layout ----------------
__global__ void __launch_bounds__(512) prep_kernel(const float* __restrict__ q,
                                                   const float* __restrict__ kv) {
    size_t idx = (size_t)blockIdx.x * 512 + threadIdx.x;  // float4 id (exact grid)
    size_t row = idx >> 7;                                // 128 float4 per 512-row
    int    dp  = (int)(idx & 127) << 2;

    {   // q scaled by CLOG2E, split into hi+lo
        float4 a = reinterpret_cast<const float4*>(q)[idx];
        float sx = a.x * CLOG2E, sy = a.y * CLOG2E, sz = a.z * CLOG2E, sw = a.w * CLOG2E;
        __nv_bfloat16 hx = __float2bfloat16(sx), hy = __float2bfloat16(sy);
        __nv_bfloat16 hz = __float2bfloat16(sz), hw = __float2bfloat16(sw);
        __nv_bfloat16 lx = __float2bfloat16(sx - __bfloat162float(hx));
        __nv_bfloat16 ly = __float2bfloat16(sy - __bfloat162float(hy));
        __nv_bfloat16 lz = __float2bfloat16(sz - __bfloat162float(hz));
        __nv_bfloat16 lw = __float2bfloat16(sw - __bfloat162float(hw));
        __nv_bfloat16* base = g_qcat + row * KSTORE + dp;
        reinterpret_cast<__nv_bfloat162*>(base)[0]       = __halves2bfloat162(hx, hy);
        reinterpret_cast<__nv_bfloat162*>(base)[1]       = __halves2bfloat162(hz, hw);
        reinterpret_cast<__nv_bfloat162*>(base + 512)[0] = __halves2bfloat162(lx, ly);
        reinterpret_cast<__nv_bfloat162*>(base + 512)[1] = __halves2bfloat162(lz, lw);
    }
    {   // kv unscaled, split into hi+lo
        float4 a = reinterpret_cast<const float4*>(kv)[idx];
        __nv_bfloat16 hx = __float2bfloat16(a.x), hy = __float2bfloat16(a.y);
        __nv_bfloat16 hz = __float2bfloat16(a.z), hw = __float2bfloat16(a.w);
        __nv_bfloat16 lx = __float2bfloat16(a.x - __bfloat162float(hx));
        __nv_bfloat16 ly = __float2bfloat16(a.y - __bfloat162float(hy));
        __nv_bfloat16 lz = __float2bfloat16(a.z - __bfloat162float(hz));
        __nv_bfloat16 lw = __float2bfloat16(a.w - __bfloat162float(hw));
        __nv_bfloat16* base = g_kcat + row * KSTORE + dp;
        reinterpret_cast<__nv_bfloat162*>(base)[0]       = __halves2bfloat162(hx, hy);
        reinterpret_cast<__nv_bfloat162*>(base)[1]       = __halves2bfloat162(hz, hw);
        reinterpret_cast<__nv_bfloat162*>(base + 512)[0] = __halves2bfloat162(lx, ly);
        reinterpret_cast<__nv_bfloat162*>(base + 512)[1] = __halves2bfloat162(lz, lw);
    }
}

// ---------------- exact fp32 diagonal: 2^(c * <q_n, kv_n>) ----------------
__global__ void __launch_bounds__(256) diag_kernel(const float* __restrict__ q,
                                                   const float* __restrict__ kv) {
    int row  = blockIdx.x * 8 + (threadIdx.x >> 5);
    int lane = threadIdx.x & 31;
    const float* qr = q  + (size_t)row * DDIM;
    const float* kr = kv + (size_t)row * DDIM;
    float s = 0.f;
#pragma unroll
    for (int i = 0; i < 16; ++i) s += qr[lane + 32 * i] * kr[lane + 32 * i];
#pragma unroll
    for (int off = 16; off; off >>= 1) s += __shfl_xor_sync(0xffffffffu, s, off);
    if (lane == 0) g_diagexp[row] = exp2f(CLOG2E * s);
}

// ---------------- main fused GEMM + normalizer kernel ----------------
__global__ void __launch_bounds__(256, 1) main_kernel(float* __restrict__ out) {
    extern __shared__ char smem_raw[];
    const uint32_t base = (smem_u32(smem_raw) + 1023u) & ~1023u;
    const uint32_t st0  = base;
    float* racc = reinterpret_cast<float*>(smem_raw +
                     ((base + STAGES * STB) - smem_u32(smem_raw)));

    const int tid  = threadIdx.x;
    const int wid  = tid >> 5;
    const int lane = tid & 31;
    const int bid  = blockIdx.x;

    if (tid < MT) racc[tid] = 0.f;

    // per-thread cp.async vector descriptors (16B vectors)
    int qoff[4]; uint32_t qdst[4];
#pragma unroll
    for (int i = 0; i < 4; ++i) {
        int v = tid + i * 256, r = v >> 3, j = v & 7;
        qoff[i] = r * KSTORE + j * 8;
        qdst[i] = sw128((uint32_t)(r * 128 + j * 16));
    }
    int koff[8]; uint32_t kdst[8];
#pragma unroll
    for (int i = 0; i < 8; ++i) {
        int v = tid + i * 256, r = v >> 3, j = v & 7;
        koff[i] = r * KSTORE + j * 8;
        kdst[i] = sw128((uint32_t)(r * 128 + j * 16));
    }

    const __nv_bfloat16* qg = g_qcat + (size_t)bid * MT * KSTORE;
    const __nv_bfloat16* kg = g_kcat + (size_t)(bid >> 5) * NSEQ * KSTORE;

    // chunk c within an N-tile: term 0 = qh*kh, 1 = ql*kh, 2 = qh*kl
    auto issue = [&](int it) {
        const int nt = it / NCH, c = it - nt * NCH;
        const int term = c >> 3, cc = c & 7;
        const int qcol = ((term == 1) ? 512 : 0) + cc * KC;
        const int kcol = ((term == 2) ? 512 : 0) + cc * KC;
        const uint32_t sA = st0 + (it & 3) * STB;
        const uint32_t sB = sA + ABYTES;
        const __nv_bfloat16* qs = qg + qcol;
#pragma unroll
        for (int i = 0; i < 4; ++i) cp_async16(sA + qdst[i], qs + qoff[i]);
        const __nv_bfloat16* ks = kg + (size_t)nt * NTILE * KSTORE + kcol;
#pragma unroll
        for (int i = 0; i < 8; ++i) cp_async16(sB + kdst[i], ks + koff[i]);
        cp_commit();
    };

    // warp tile: 2 M-warps x 4 N-warps, each 64x64
    const int m0 = (wid & 1) * 64;
    const int n0 = (wid >> 1) * 64;
    const int lr  = lane & 15;          // ldmatrix row within 16
    const int lcb = (lane >> 4) * 16;   // ldmatrix 16B column group

    uint32_t aBase[4], aSw[4], bBase[4], bSw[4];
#pragma unroll
    for (int f = 0; f < 4; ++f) {
        int ra = m0 + f * 16 + lr;
        aBase[f] = (uint32_t)(ra * 128); aSw[f] = (uint32_t)((ra & 7) << 4);
        int rb = n0 + f * 16 + lr;
        bBase[f] = (uint32_t)(rb * 128); bSw[f] = (uint32_t)((rb & 7) << 4);
    }

    float c[4][8][4];
#pragma unroll
    for (int mf = 0; mf < 4; ++mf)
#pragma unroll
        for (int nf = 0; nf < 8; ++nf)
#pragma unroll
            for (int k = 0; k < 4; ++k) c[mf][nf][k] = 0.f;

    issue(0);
    issue(1);
    issue(2);

    uint32_t afr[2][4][4], bfr[2][4][4];

    for (int it = 0; it < TOTAL; ++it) {
        if (it <= TOTAL - 3)      cp_wait_group<2>();
        else if (it == TOTAL - 2) cp_wait_group<1>();
        else                      cp_wait_group<0>();
        __syncthreads();
        if (it + 3 < TOTAL) issue(it + 3);

        const uint32_t sA = st0 + (it & 3) * STB;
        const uint32_t sB = sA + ABYTES;

        {   // prime kk=0 fragments
            const uint32_t cb = lcb;
#pragma unroll
            for (int f = 0; f < 4; ++f) ldsm4(afr[0][f], sA + aBase[f] + (cb ^ aSw[f]));
#pragma unroll
            for (int f = 0; f < 4; ++f) ldsm4(bfr[0][f], sB + bBase[f] + (cb ^ bSw[f]));
        }

#pragma unroll
        for (int kk = 0; kk < 4; ++kk) {
            const int cur = kk & 1;
            if (kk < 3) {   // prefetch kk+1 fragments into the other buffer
                const uint32_t cb = (uint32_t)((kk + 1) * 32) + lcb;
#pragma unroll
                for (int f = 0; f < 4; ++f)
                    ldsm4(afr[cur ^ 1][f], sA + aBase[f] + (cb ^ aSw[f]));
#pragma unroll
                for (int f = 0; f < 4; ++f)
                    ldsm4(bfr[cur ^ 1][f], sB + bBase[f] + (cb ^ bSw[f]));
            }
#pragma unroll
            for (int mf = 0; mf < 4; ++mf)
#pragma unroll
                for (int g = 0; g < 4; ++g) {
                    mma16816(c[mf][2 * g],     afr[cur][mf], bfr[cur][g][0], bfr[cur][g][2]);
                    mma16816(c[mf][2 * g + 1], afr[cur][mf], bfr[cur][g][1], bfr[cur][g][3]);
                }
        }

        if (it % NCH == NCH - 1) {
            // epilogue for this 256-col kv tile: rowsum of 2^score
#pragma unroll
            for (int mf = 0; mf < 4; ++mf) {
                float s0 = 0.f, s1 = 0.f;
#pragma unroll
                for (int nf = 0; nf < 8; ++nf) {
                    s0 += ex2(c[mf][nf][0]) + ex2(c[mf][nf][1]);
                    s1 += ex2(c[mf][nf][2]) + ex2(c[mf][nf][3]);
                    c[mf][nf][0] = 0.f; c[mf][nf][1] = 0.f;
                    c[mf][nf][2] = 0.f; c[mf][nf][3] = 0.f;
                }
                s0 += __shfl_xor_sync(0xffffffffu, s0, 1);
                s0 += __shfl_xor_sync(0xffffffffu, s0, 2);
                s1 += __shfl_xor_sync(0xffffffffu, s1, 1);
                s1 += __shfl_xor_sync(0xffffffffu, s1, 2);
                if ((lane & 3) == 0) {
                    atomicAdd(&racc[m0 + mf * 16 + (lane >> 2)], s0);
                    atomicAdd(&racc[m0 + mf * 16 + 8 + (lane >> 2)], s1);
                }
            }
        }
    }

    __syncthreads();
    if (tid < MT) {
        const int row = bid * MT + tid;
        out[row] = g_diagexp[row] / racc[tid];
    }
}

extern "C" void kernel_launch(void* const* d_in, const int* in_sizes, int n_in,
                              void* d_out, int out_size) {
    const float* q  = (const float*)d_in[0];
    const float* kv = (const float*)d_in[1];
    float* out = (float*)d_out;

    prep_kernel<<<4096, 512>>>(q, kv);
    diag_kernel<<<2048, 256>>>(q, kv);

    cudaFuncSetAttribute(main_kernel, cudaFuncAttributeMaxDynamicSharedMemorySize,
                         SMEM_TOTAL);
    main_kernel<<<BATCH * (NSEQ / MT), 256, SMEM_TOTAL>>>(out);
}

// round 5
// speedup vs baseline: 1.5843x; 1.5254x over previous
#include <cuda_runtime.h>
#include <cuda_fp16.h>
#include <cstdint>

#define DEVINL __device__ __forceinline__

// ---------------- problem constants ----------------
static constexpr int BATCH = 4;
static constexpr int NSEQ  = 4096;
static constexpr int DDIM  = 512;
// scale * log2(e): logits kept in log2 domain so epilogue is a bare ex2.approx
static constexpr float CLOG2E = 0.09016844005556021f;

// ---------------- tiling ----------------
static constexpr int MT    = 128;            // q rows per CTA
static constexpr int NTILE = 256;            // kv rows per accumulation tile
static constexpr int KQ    = 1024;           // qcat row: [qh(512) | ql(512)]  fp16
static constexpr int KK    = 512;            // kcat row: [kh(512)]            fp16
static constexpr int KC    = 64;             // k per chunk (128B smem rows)
static constexpr int DC    = 8;              // double-chunks per N-tile (512/64)
static constexpr int NTC   = NSEQ / NTILE;   // 16 N-tiles
static constexpr int TOTAL = NTC * DC;       // 128 pipeline iterations
static constexpr int STAGES = 3;

static constexpr int AB  = MT * KC * 2;          // 16384 per A term
static constexpr int BB  = NTILE * KC * 2;       // 32768
static constexpr int STB = 2 * AB + BB;          // 65536 per stage
static constexpr int SMEM_TOTAL = 1024 + STAGES * STB + 512;  // slack + racc

// ---------------- scratch (device globals: no allocs allowed) ----------------
__device__ __align__(1024) __half g_qcat[(size_t)BATCH * NSEQ * KQ];
__device__ __align__(1024) __half g_kcat[(size_t)BATCH * NSEQ * KK];
__device__ float g_diagexp[BATCH * NSEQ];

// ---------------- PTX helpers ----------------
DEVINL uint32_t smem_u32(const void* p) {
    uint32_t a;
    asm("{ .reg .u64 t; cvta.to.shared.u64 t, %1; cvt.u32.u64 %0, t; }"
        : "=r"(a) : "l"(p));
    return a;
}
DEVINL uint32_t sw128(uint32_t off) { return off ^ ((off >> 3) & 0x70); }

DEVINL void cp_async16(uint32_t dst, const void* src) {
    asm volatile("cp.async.cg.shared.global [%0], [%1], 16;"
                 :: "r"(dst), "l"(src) : "memory");
}
DEVINL void cp_commit() { asm volatile("cp.async.commit_group;" ::: "memory"); }
template <int N>
DEVINL void cp_wait_group() { asm volatile("cp.async.wait_group %0;" :: "n"(N) : "memory"); }

DEVINL void ldsm4(uint32_t (&r)[4], uint32_t addr) {
    asm volatile("ldmatrix.sync.aligned.m8n8.x4.shared.b16 {%0,%1,%2,%3}, [%4];"
                 : "=r"(r[0]), "=r"(r[1]), "=r"(r[2]), "=r"(r[3]) : "r"(addr));
}
DEVINL void mma16816(float* d, const uint32_t* a, uint32_t b0, uint32_t b1) {
    asm volatile(
        "mma.sync.aligned.m16n8k16.row.col.f32.f16.f16.f32 "
        "{%0,%1,%2,%3}, {%4,%5,%6,%7}, {%8,%9}, {%0,%1,%2,%3};"
        : "+f"(d[0]), "+f"(d[1]), "+f"(d[2]), "+f"(d[3])
        : "r"(a[0]), "r"(a[1]), "r"(a[2]), "r"(a[3]), "r"(b0), "r"(b1));
}
DEVINL float ex2(float x) {
    float y;
    asm("ex2.approx.ftz.f32 %0, %1;" : "=f"(y) : "f"(x));
    return y;
}

// ---------------- prep: q -> fp16 hi/lo split (scaled), k -> fp16 hi ----------------
__global__ void __launch_bounds__(512) prep_kernel(const float* __restrict__ q,
                                                   const float* __restrict__ kv) {
    size_t idx = (size_t)blockIdx.x * 512 + threadIdx.x;  // float4 id (exact grid)
    size_t row = idx >> 7;                                // 128 float4 per 512-row
    int    dp  = (int)(idx & 127) << 2;

    {   // q scaled by CLOG2E, split into fp16 hi + lo
        float4 a = reinterpret_cast<const float4*>(q)[idx];
        float sx = a.x * CLOG2E, sy = a.y * CLOG2E, sz = a.z * CLOG2E, sw = a.w * CLOG2E;
        __half hx = __float2half(sx), hy = __float2half(sy);
        __half hz = __float2half(sz), hw = __float2half(sw);
        __half lx = __float2half(sx - __half2float(hx));
        __half ly = __float2half(sy - __half2float(hy));
        __half lz = __float2half(sz - __half2float(hz));
        __half lw = __float2half(sw - __half2float(hw));
        __half* base = g_qcat + row * KQ + dp;
        reinterpret_cast<__half2*>(base)[0]       = __halves2half2(hx, hy);
        reinterpret_cast<__half2*>(base)[1]       = __halves2half2(hz, hw);
        reinterpret_cast<__half2*>(base + 512)[0] = __halves2half2(lx, ly);
        reinterpret_cast<__half2*>(base + 512)[1] = __halves2half2(lz, lw);
    }
    {   // kv: fp16 hi only
        float4 a = reinterpret_cast<const float4*>(kv)[idx];
        __half* base = g_kcat + row * KK + dp;
        reinterpret_cast<__half2*>(base)[0] =
            __halves2half2(__float2half(a.x), __float2half(a.y));
        reinterpret_cast<__half2*>(base)[1] =
            __halves2half2(__float2half(a.z), __float2half(a.w));
    }
}

// ---------------- exact fp32 diagonal: 2^(c * <q_n, kv_n>) ----------------
__global__ void __launch_bounds__(256) diag_kernel(const float* __restrict__ q,
                                                   const float* __restrict__ kv) {
    int row  = blockIdx.x * 8 + (threadIdx.x >> 5);
    int lane = threadIdx.x & 31;
    const float* qr = q  + (size_t)row * DDIM;
    const float* kr = kv + (size_t)row * DDIM;
    float s = 0.f;
#pragma unroll
    for (int i = 0; i < 16; ++i) s += qr[lane + 32 * i] * kr[lane + 32 * i];
#pragma unroll
    for (int off = 16; off; off >>= 1) s += __shfl_xor_sync(0xffffffffu, s, off);
    if (lane == 0) g_diagexp[row] = exp2f(CLOG2E * s);
}

// ---------------- main fused GEMM + normalizer kernel ----------------
__global__ void __launch_bounds__(256, 1) main_kernel(float* __restrict__ out) {
    extern __shared__ char smem_raw[];
    const uint32_t base = (smem_u32(smem_raw) + 1023u) & ~1023u;
    const uint32_t st0  = base;
    float* racc = reinterpret_cast<float*>(smem_raw +
                     ((base + STAGES * STB) - smem_u32(smem_raw)));

    const int tid  = threadIdx.x;
    const int wid  = tid >> 5;
    const int lane = tid & 31;
    const int bid  = blockIdx.x;

    if (tid < MT) racc[tid] = 0.f;

    // per-thread cp.async vector descriptors (16B vectors)
    int qoff[4]; uint32_t qdst[4];
#pragma unroll
    for (int i = 0; i < 4; ++i) {
        int v = tid + i * 256, r = v >> 3, j = v & 7;
        qoff[i] = r * KQ + j * 8;
        qdst[i] = sw128((uint32_t)(r * 128 + j * 16));
    }
    int koff[8]; uint32_t kdst[8];
#pragma unroll
    for (int i = 0; i < 8; ++i) {
        int v = tid + i * 256, r = v >> 3, j = v & 7;
        koff[i] = r * KK + j * 8;
        kdst[i] = sw128((uint32_t)(r * 128 + j * 16));
    }

    const __half* qg = g_qcat + (size_t)bid * MT * KQ;
    const __half* kg = g_kcat + (size_t)(bid >> 5) * NSEQ * KK;

    // double-chunk it: nt = it/8, cc = it%8; loads A_h, A_l (q cols cc*64 and
    // 512+cc*64) and one shared B (kh cols cc*64)
    auto issue = [&](int it) {
        const int nt = it >> 3, cc = it & 7;
        const uint32_t sAh = st0 + (it % STAGES) * STB;
        const uint32_t sAl = sAh + AB;
        const uint32_t sB  = sAh + 2 * AB;
        const __half* qs = qg + cc * KC;
#pragma unroll
        for (int i = 0; i < 4; ++i) cp_async16(sAh + qdst[i], qs + qoff[i]);
#pragma unroll
        for (int i = 0; i < 4; ++i) cp_async16(sAl + qdst[i], qs + 512 + qoff[i]);
        const __half* ks = kg + (size_t)nt * NTILE * KK + cc * KC;
#pragma unroll
        for (int i = 0; i < 8; ++i) cp_async16(sB + kdst[i], ks + koff[i]);
        cp_commit();
    };

    // warp tile: 2 M-warps x 4 N-warps, each 64x64
    const int m0 = (wid & 1) * 64;
    const int n0 = (wid >> 1) * 64;
    const int lr  = lane & 15;          // ldmatrix row within 16
    const int lcb = (lane >> 4) * 16;   // ldmatrix 16B column group

    uint32_t aBase[4], aSw[4], bBase[4], bSw[4];
#pragma unroll
    for (int f = 0; f < 4; ++f) {
        int ra = m0 + f * 16 + lr;
        aBase[f] = (uint32_t)(ra * 128); aSw[f] = (uint32_t)((ra & 7) << 4);
        int rb = n0 + f * 16 + lr;
        bBase[f] = (uint32_t)(rb * 128); bSw[f] = (uint32_t)((rb & 7) << 4);
    }

    float c[4][8][4];
#pragma unroll
    for (int mf = 0; mf < 4; ++mf)
#pragma unroll
        for (int nf = 0; nf < 8; ++nf)
#pragma unroll
            for (int k = 0; k < 4; ++k) c[mf][nf][k] = 0.f;

    issue(0);
    issue(1);

    for (int it = 0; it < TOTAL; ++it) {
        if (it < TOTAL - 1) cp_wait_group<1>();
        else                cp_wait_group<0>();
        __syncthreads();
        if (it + 2 < TOTAL) issue(it + 2);

        const uint32_t sAh = st0 + (it % STAGES) * STB;
        const uint32_t sAl = sAh + AB;
        const uint32_t sB  = sAh + 2 * AB;

#pragma unroll
        for (int kk = 0; kk < 4; ++kk) {
            const uint32_t cb = (uint32_t)(kk * 32) + lcb;
            uint32_t b[4][4], ah[4][4], al[4][4];
#pragma unroll
            for (int f = 0; f < 4; ++f) ldsm4(b[f],  sB  + bBase[f] + (cb ^ bSw[f]));
#pragma unroll
            for (int f = 0; f < 4; ++f) ldsm4(ah[f], sAh + aBase[f] + (cb ^ aSw[f]));
#pragma unroll
            for (int f = 0; f < 4; ++f) ldsm4(al[f], sAl + aBase[f] + (cb ^ aSw[f]));
            // hi term
#pragma unroll
            for (int mf = 0; mf < 4; ++mf)
#pragma unroll
                for (int g = 0; g < 4; ++g) {
                    mma16816(c[mf][2 * g],     ah[mf], b[g][0], b[g][2]);
                    mma16816(c[mf][2 * g + 1], ah[mf], b[g][1], b[g][3]);
                }
            // lo term (same accumulators, same B fragments)
#pragma unroll
            for (int mf = 0; mf < 4; ++mf)
#pragma unroll
                for (int g = 0; g < 4; ++g) {
                    mma16816(c[mf][2 * g],     al[mf], b[g][0], b[g][2]);
                    mma16816(c[mf][2 * g + 1], al[mf], b[g][1], b[g][3]);
                }
        }

        if ((it & 7) == 7) {
            // epilogue for this 256-col kv tile: rowsum of 2^score
#pragma unroll
            for (int mf = 0; mf < 4; ++mf) {
                float s0 = 0.f, s1 = 0.f;
#pragma unroll
                for (int nf = 0; nf < 8; ++nf) {
                    s0 += ex2(c[mf][nf][0]) + ex2(c[mf][nf][1]);
                    s1 += ex2(c[mf][nf][2]) + ex2(c[mf][nf][3]);
                    c[mf][nf][0] = 0.f; c[mf][nf][1] = 0.f;
                    c[mf][nf][2] = 0.f; c[mf][nf][3] = 0.f;
                }
                s0 += __shfl_xor_sync(0xffffffffu, s0, 1);
                s0 += __shfl_xor_sync(0xffffffffu, s0, 2);
                s1 += __shfl_xor_sync(0xffffffffu, s1, 1);
                s1 += __shfl_xor_sync(0xffffffffu, s1, 2);
                if ((lane & 3) == 0) {
                    atomicAdd(&racc[m0 + mf * 16 + (lane >> 2)], s0);
                    atomicAdd(&racc[m0 + mf * 16 + 8 + (lane >> 2)], s1);
                }
            }
        }
    }

    __syncthreads();
    if (tid < MT) {
        const int row = bid * MT + tid;
        out[row] = g_diagexp[row] / racc[tid];
    }
}

extern "C" void kernel_launch(void* const* d_in, const int* in_sizes, int n_in,
                              void* d_out, int out_size) {
    const float* q  = (const float*)d_in[0];
    const float* kv = (const float*)d_in[1];
    float* out = (float*)d_out;

    prep_kernel<<<4096, 512>>>(q, kv);
    diag_kernel<<<2048, 256>>>(q, kv);

    cudaFuncSetAttribute(main_kernel, cudaFuncAttributeMaxDynamicSharedMemorySize,
                         SMEM_TOTAL);
    main_kernel<<<BATCH * (NSEQ / MT), 256, SMEM_TOTAL>>>(out);
}

// round 6
// speedup vs baseline: 1.6998x; 1.0729x over previous
#include <cuda_runtime.h>
#include <cuda_fp16.h>
#include <cstdint>

#define DEVINL __device__ __forceinline__

// ---------------- problem constants ----------------
static constexpr int BATCH = 4;
static constexpr int NSEQ  = 4096;
static constexpr int DDIM  = 512;
// scale * log2(e): logits kept in log2 domain so epilogue is a bare ex2.approx
static constexpr float CLOG2E = 0.09016844005556021f;
static constexpr float LOSCALE = 1024.0f;          // lo term stored pre-scaled
static constexpr float LOINV   = 1.0f / 1024.0f;   // undone in epilogue

// ---------------- tiling ----------------
static constexpr int MT    = 128;            // q rows per CTA
static constexpr int NTILE = 256;            // kv rows per accumulation tile
static constexpr int KQ    = 1024;           // qcat row: [qh(512) | ql(512)]  fp16
static constexpr int KK    = 512;            // kcat row: [kh(512)]            fp16
static constexpr int KC    = 64;             // k per chunk (128B smem rows)
static constexpr int NTC   = NSEQ / NTILE;   // 16 N-tiles
static constexpr int TOTAL = NTC * 8;        // 128 pipeline iterations
static constexpr int STAGES = 3;

static constexpr int AB  = MT * KC * 2;          // 16384 per A term
static constexpr int BB  = NTILE * KC * 2;       // 32768
static constexpr int STB = 2 * AB + BB;          // 65536 per stage
static constexpr int SMEM_TOTAL = 1024 + STAGES * STB + 512;  // slack + racc

// ---------------- scratch (device globals: no allocs allowed) ----------------
__device__ __align__(1024) __half g_qcat[(size_t)BATCH * NSEQ * KQ];
__device__ __align__(1024) __half g_kcat[(size_t)BATCH * NSEQ * KK];
__device__ float g_diagexp[BATCH * NSEQ];

// ---------------- PTX helpers ----------------
DEVINL uint32_t smem_u32(const void* p) {
    uint32_t a;
    asm("{ .reg .u64 t; cvta.to.shared.u64 t, %1; cvt.u32.u64 %0, t; }"
        : "=r"(a) : "l"(p));
    return a;
}
DEVINL uint32_t sw128(uint32_t off) { return off ^ ((off >> 3) & 0x70); }

DEVINL void cp_async16(uint32_t dst, const void* src) {
    asm volatile("cp.async.cg.shared.global [%0], [%1], 16;"
                 :: "r"(dst), "l"(src) : "memory");
}
DEVINL void cp_commit() { asm volatile("cp.async.commit_group;" ::: "memory"); }
template <int N>
DEVINL void cp_wait_group() { asm volatile("cp.async.wait_group %0;" :: "n"(N) : "memory"); }

DEVINL void ldsm4(uint32_t (&r)[4], uint32_t addr) {
    asm volatile("ldmatrix.sync.aligned.m8n8.x4.shared.b16 {%0,%1,%2,%3}, [%4];"
                 : "=r"(r[0]), "=r"(r[1]), "=r"(r[2]), "=r"(r[3]) : "r"(addr));
}
// fp16-accumulate MMA: D (2 regs = 4 halves) += A*B
DEVINL void mma_f16acc(uint32_t* d, const uint32_t* a, uint32_t b0, uint32_t b1) {
    asm volatile(
        "mma.sync.aligned.m16n8k16.row.col.f16.f16.f16.f16 "
        "{%0,%1}, {%2,%3,%4,%5}, {%6,%7}, {%0,%1};"
        : "+r"(d[0]), "+r"(d[1])
        : "r"(a[0]), "r"(a[1]), "r"(a[2]), "r"(a[3]), "r"(b0), "r"(b1));
}
DEVINL float ex2(float x) {
    float y;
    asm("ex2.approx.ftz.f32 %0, %1;" : "=f"(y) : "f"(x));
    return y;
}

// ---------------- prep: q -> fp16 hi/lo split (scaled), k -> fp16 hi ----------------
__global__ void __launch_bounds__(512) prep_kernel(const float* __restrict__ q,
                                                   const float* __restrict__ kv) {
    size_t idx = (size_t)blockIdx.x * 512 + threadIdx.x;  // float4 id (exact grid)
    size_t row = idx >> 7;                                // 128 float4 per 512-row
    int    dp  = (int)(idx & 127) << 2;

    {   // q scaled by CLOG2E, split into fp16 hi + lo (lo pre-scaled by 2^10)
        float4 a = reinterpret_cast<const float4*>(q)[idx];
        float sx = a.x * CLOG2E, sy = a.y * CLOG2E, sz = a.z * CLOG2E, sw = a.w * CLOG2E;
        __half hx = __float2half(sx), hy = __float2half(sy);
        __half hz = __float2half(sz), hw = __float2half(sw);
        __half lx = __float2half((sx - __half2float(hx)) * LOSCALE);
        __half ly = __float2half((sy - __half2float(hy)) * LOSCALE);
        __half lz = __float2half((sz - __half2float(hz)) * LOSCALE);
        __half lw = __float2half((sw - __half2float(hw)) * LOSCALE);
        __half* base = g_qcat + row * KQ + dp;
        reinterpret_cast<__half2*>(base)[0]       = __halves2half2(hx, hy);
        reinterpret_cast<__half2*>(base)[1]       = __halves2half2(hz, hw);
        reinterpret_cast<__half2*>(base + 512)[0] = __halves2half2(lx, ly);
        reinterpret_cast<__half2*>(base + 512)[1] = __halves2half2(lz, lw);
    }
    {   // kv: fp16 hi only
        float4 a = reinterpret_cast<const float4*>(kv)[idx];
        __half* base = g_kcat + row * KK + dp;
        reinterpret_cast<__half2*>(base)[0] =
            __halves2half2(__float2half(a.x), __float2half(a.y));
        reinterpret_cast<__half2*>(base)[1] =
            __halves2half2(__float2half(a.z), __float2half(a.w));
    }
}

// ---------------- exact fp32 diagonal: 2^(c * <q_n, kv_n>) ----------------
__global__ void __launch_bounds__(256) diag_kernel(const float* __restrict__ q,
                                                   const float* __restrict__ kv) {
    int row  = blockIdx.x * 8 + (threadIdx.x >> 5);
    int lane = threadIdx.x & 31;
    const float* qr = q  + (size_t)row * DDIM;
    const float* kr = kv + (size_t)row * DDIM;
    float s = 0.f;
#pragma unroll
    for (int i = 0; i < 16; ++i) s += qr[lane + 32 * i] * kr[lane + 32 * i];
#pragma unroll
    for (int off = 16; off; off >>= 1) s += __shfl_xor_sync(0xffffffffu, s, off);
    if (lane == 0) g_diagexp[row] = exp2f(CLOG2E * s);
}

// ---------------- main fused GEMM + normalizer kernel ----------------
__global__ void __launch_bounds__(256, 1) main_kernel(float* __restrict__ out) {
    extern __shared__ char smem_raw[];
    const uint32_t base = (smem_u32(smem_raw) + 1023u) & ~1023u;
    const uint32_t st0  = base;
    float* racc = reinterpret_cast<float*>(smem_raw +
                     ((base + STAGES * STB) - smem_u32(smem_raw)));

    const int tid  = threadIdx.x;
    const int wid  = tid >> 5;
    const int lane = tid & 31;
    const int bid  = blockIdx.x;

    if (tid < MT) racc[tid] = 0.f;

    // per-thread cp.async vector descriptors (16B vectors)
    int qoff[4]; uint32_t qdst[4];
#pragma unroll
    for (int i = 0; i < 4; ++i) {
        int v = tid + i * 256, r = v >> 3, j = v & 7;
        qoff[i] = r * KQ + j * 8;
        qdst[i] = sw128((uint32_t)(r * 128 + j * 16));
    }
    int koff[8]; uint32_t kdst[8];
#pragma unroll
    for (int i = 0; i < 8; ++i) {
        int v = tid + i * 256, r = v >> 3, j = v & 7;
        koff[i] = r * KK + j * 8;
        kdst[i] = sw128((uint32_t)(r * 128 + j * 16));
    }

    const __half* qg = g_qcat + (size_t)bid * MT * KQ;
    const __half* kg = g_kcat + (size_t)(bid >> 5) * NSEQ * KK;

    // double-chunk it: nt = it/8, cc = it%8; loads A_h, A_l and one shared B
    auto issue = [&](int it) {
        const int nt = it >> 3, cc = it & 7;
        const uint32_t sAh = st0 + (it % STAGES) * STB;
        const uint32_t sAl = sAh + AB;
        const uint32_t sB  = sAh + 2 * AB;
        const __half* qs = qg + cc * KC;
#pragma unroll
        for (int i = 0; i < 4; ++i) cp_async16(sAh + qdst[i], qs + qoff[i]);
#pragma unroll
        for (int i = 0; i < 4; ++i) cp_async16(sAl + qdst[i], qs + 512 + qoff[i]);
        const __half* ks = kg + (size_t)nt * NTILE * KK + cc * KC;
#pragma unroll
        for (int i = 0; i < 8; ++i) cp_async16(sB + kdst[i], ks + koff[i]);
        cp_commit();
    };

    // warp tile: 2 M-warps x 4 N-warps, each 64x64
    const int m0 = (wid & 1) * 64;
    const int n0 = (wid >> 1) * 64;
    const int lr  = lane & 15;          // ldmatrix row within 16
    const int lcb = (lane >> 4) * 16;   // ldmatrix 16B column group

    uint32_t aBase[4], aSw[4], bBase[4], bSw[4];
#pragma unroll
    for (int f = 0; f < 4; ++f) {
        int ra = m0 + f * 16 + lr;
        aBase[f] = (uint32_t)(ra * 128); aSw[f] = (uint32_t)((ra & 7) << 4);
        int rb = n0 + f * 16 + lr;
        bBase[f] = (uint32_t)(rb * 128); bSw[f] = (uint32_t)((rb & 7) << 4);
    }

    // fp16 accumulators: hi and lo kept separate, combined in fp32 at epilogue
    uint32_t ch[4][8][2], cl[4][8][2];
#pragma unroll
    for (int mf = 0; mf < 4; ++mf)
#pragma unroll
        for (int nf = 0; nf < 8; ++nf) {
            ch[mf][nf][0] = 0u; ch[mf][nf][1] = 0u;
            cl[mf][nf][0] = 0u; cl[mf][nf][1] = 0u;
        }

    issue(0);
    issue(1);

    for (int it = 0; it < TOTAL; ++it) {
        if (it < TOTAL - 1) cp_wait_group<1>();
        else                cp_wait_group<0>();
        __syncthreads();
        if (it + 2 < TOTAL) issue(it + 2);

        const uint32_t sAh = st0 + (it % STAGES) * STB;
        const uint32_t sAl = sAh + AB;
        const uint32_t sB  = sAh + 2 * AB;

#pragma unroll
        for (int kk = 0; kk < 4; ++kk) {
            const uint32_t cb = (uint32_t)(kk * 32) + lcb;
            uint32_t b[4][4], ah[4][4], al[4][4];
#pragma unroll
            for (int f = 0; f < 4; ++f) ldsm4(b[f],  sB  + bBase[f] + (cb ^ bSw[f]));
#pragma unroll
            for (int f = 0; f < 4; ++f) ldsm4(ah[f], sAh + aBase[f] + (cb ^ aSw[f]));
#pragma unroll
            for (int f = 0; f < 4; ++f) ldsm4(al[f], sAl + aBase[f] + (cb ^ aSw[f]));
            // hi term
#pragma unroll
            for (int mf = 0; mf < 4; ++mf)
#pragma unroll
                for (int g = 0; g < 4; ++g) {
                    mma_f16acc(ch[mf][2 * g],     ah[mf], b[g][0], b[g][2]);
                    mma_f16acc(ch[mf][2 * g + 1], ah[mf], b[g][1], b[g][3]);
                }
            // lo term (separate fp16 accumulators, same B fragments)
#pragma unroll
            for (int mf = 0; mf < 4; ++mf)
#pragma unroll
                for (int g = 0; g < 4; ++g) {
                    mma_f16acc(cl[mf][2 * g],     al[mf], b[g][0], b[g][2]);
                    mma_f16acc(cl[mf][2 * g + 1], al[mf], b[g][1], b[g][3]);
                }
        }

        if ((it & 7) == 7) {
            // epilogue for this 256-col kv tile: rowsum of 2^(hi + lo/1024)
#pragma unroll
            for (int mf = 0; mf < 4; ++mf) {
                float s0 = 0.f, s1 = 0.f;
#pragma unroll
                for (int nf = 0; nf < 8; ++nf) {
                    float2 h0 = __half22float2(*reinterpret_cast<__half2*>(&ch[mf][nf][0]));
                    float2 h1 = __half22float2(*reinterpret_cast<__half2*>(&ch[mf][nf][1]));
                    float2 l0 = __half22float2(*reinterpret_cast<__half2*>(&cl[mf][nf][0]));
                    float2 l1 = __half22float2(*reinterpret_cast<__half2*>(&cl[mf][nf][1]));
                    s0 += ex2(fmaf(l0.x, LOINV, h0.x)) + ex2(fmaf(l0.y, LOINV, h0.y));
                    s1 += ex2(fmaf(l1.x, LOINV, h1.x)) + ex2(fmaf(l1.y, LOINV, h1.y));
                    ch[mf][nf][0] = 0u; ch[mf][nf][1] = 0u;
                    cl[mf][nf][0] = 0u; cl[mf][nf][1] = 0u;
                }
                s0 += __shfl_xor_sync(0xffffffffu, s0, 1);
                s0 += __shfl_xor_sync(0xffffffffu, s0, 2);
                s1 += __shfl_xor_sync(0xffffffffu, s1, 1);
                s1 += __shfl_xor_sync(0xffffffffu, s1, 2);
                if ((lane & 3) == 0) {
                    atomicAdd(&racc[m0 + mf * 16 + (lane >> 2)], s0);
                    atomicAdd(&racc[m0 + mf * 16 + 8 + (lane >> 2)], s1);
                }
            }
        }
    }

    __syncthreads();
    if (tid < MT) {
        const int row = bid * MT + tid;
        out[row] = g_diagexp[row] / racc[tid];
    }
}

extern "C" void kernel_launch(void* const* d_in, const int* in_sizes, int n_in,
                              void* d_out, int out_size) {
    const float* q  = (const float*)d_in[0];
    const float* kv = (const float*)d_in[1];
    float* out = (float*)d_out;

    prep_kernel<<<4096, 512>>>(q, kv);
    diag_kernel<<<2048, 256>>>(q, kv);

    cudaFuncSetAttribute(main_kernel, cudaFuncAttributeMaxDynamicSharedMemorySize,
                         SMEM_TOTAL);
    main_kernel<<<BATCH * (NSEQ / MT), 256, SMEM_TOTAL>>>(out);
}

// round 7
// speedup vs baseline: 1.9204x; 1.1298x over previous
#include <cuda_runtime.h>
#include <cuda_fp16.h>
#include <cstdint>

#define DEVINL __device__ __forceinline__

// ---------------- problem constants ----------------
static constexpr int BATCH = 4;
static constexpr int NSEQ  = 4096;
static constexpr int DDIM  = 512;
// scale * log2(e): logits kept in log2 domain so epilogue is a bare ex2.approx
static constexpr float CLOG2E = 0.09016844005556021f;
static constexpr float LOSCALE = 1024.0f;          // lo term stored pre-scaled
static constexpr float LOINV   = 1.0f / 1024.0f;   // undone in epilogue

// ---------------- tiling ----------------
static constexpr int MT    = 128;            // q rows per unit
static constexpr int NTILE = 256;            // kv rows per unit
static constexpr int KQ    = 1024;           // qcat row: [qh(512) | ql(512)]  fp16
static constexpr int KK    = 512;            // kcat row: [kh(512)]            fp16
static constexpr int KC    = 64;             // k per chunk (128B smem rows)
static constexpr int QTILES = BATCH * NSEQ / MT;   // 128
static constexpr int NTC    = NSEQ / NTILE;        // 16
static constexpr int UNITS  = QTILES * NTC;        // 2048 work units
static constexpr int STAGES = 3;

static constexpr int AB  = MT * KC * 2;          // 16384 per A term
static constexpr int BB  = NTILE * KC * 2;       // 32768
static constexpr int STB = 2 * AB + BB;          // 65536 per stage
static constexpr int SMEM_TOTAL = 1024 + STAGES * STB;

// ---------------- scratch (device globals: no allocs allowed) ----------------
__device__ __align__(1024) __half g_qcat[(size_t)BATCH * NSEQ * KQ];
__device__ __align__(1024) __half g_kcat[(size_t)BATCH * NSEQ * KK];
__device__ float g_diagexp[BATCH * NSEQ];
__device__ float g_rsum[BATCH * NSEQ];

// ---------------- PTX helpers ----------------
DEVINL uint32_t smem_u32(const void* p) {
    uint32_t a;
    asm("{ .reg .u64 t; cvta.to.shared.u64 t, %1; cvt.u32.u64 %0, t; }"
        : "=r"(a) : "l"(p));
    return a;
}
DEVINL uint32_t sw128(uint32_t off) { return off ^ ((off >> 3) & 0x70); }

DEVINL void cp_async16(uint32_t dst, const void* src) {
    asm volatile("cp.async.cg.shared.global [%0], [%1], 16;"
                 :: "r"(dst), "l"(src) : "memory");
}
DEVINL void cp_commit() { asm volatile("cp.async.commit_group;" ::: "memory"); }
template <int N>
DEVINL void cp_wait_group() { asm volatile("cp.async.wait_group %0;" :: "n"(N) : "memory"); }

DEVINL void ldsm4(uint32_t (&r)[4], uint32_t addr) {
    asm volatile("ldmatrix.sync.aligned.m8n8.x4.shared.b16 {%0,%1,%2,%3}, [%4];"
                 : "=r"(r[0]), "=r"(r[1]), "=r"(r[2]), "=r"(r[3]) : "r"(addr));
}
// fp16-accumulate MMA: D (2 regs = 4 halves) += A*B
DEVINL void mma_f16acc(uint32_t* d, const uint32_t* a, uint32_t b0, uint32_t b1) {
    asm volatile(
        "mma.sync.aligned.m16n8k16.row.col.f16.f16.f16.f16 "
        "{%0,%1}, {%2,%3,%4,%5}, {%6,%7}, {%0,%1};"
        : "+r"(d[0]), "+r"(d[1])
        : "r"(a[0]), "r"(a[1]), "r"(a[2]), "r"(a[3]), "r"(b0), "r"(b1));
}
DEVINL float ex2(float x) {
    float y;
    asm("ex2.approx.ftz.f32 %0, %1;" : "=f"(y) : "f"(x));
    return y;
}

// ---------------- prep: q -> fp16 hi/lo split (scaled), k -> fp16 hi ----------------
__global__ void __launch_bounds__(512) prep_kernel(const float* __restrict__ q,
                                                   const float* __restrict__ kv) {
    size_t idx = (size_t)blockIdx.x * 512 + threadIdx.x;  // float4 id (exact grid)
    size_t row = idx >> 7;                                // 128 float4 per 512-row
    int    dp  = (int)(idx & 127) << 2;

    {   // q scaled by CLOG2E, split into fp16 hi + lo (lo pre-scaled by 2^10)
        float4 a = reinterpret_cast<const float4*>(q)[idx];
        float sx = a.x * CLOG2E, sy = a.y * CLOG2E, sz = a.z * CLOG2E, sw = a.w * CLOG2E;
        __half hx = __float2half(sx), hy = __float2half(sy);
        __half hz = __float2half(sz), hw = __float2half(sw);
        __half lx = __float2half((sx - __half2float(hx)) * LOSCALE);
        __half ly = __float2half((sy - __half2float(hy)) * LOSCALE);
        __half lz = __float2half((sz - __half2float(hz)) * LOSCALE);
        __half lw = __float2half((sw - __half2float(hw)) * LOSCALE);
        __half* base = g_qcat + row * KQ + dp;
        reinterpret_cast<__half2*>(base)[0]       = __halves2half2(hx, hy);
        reinterpret_cast<__half2*>(base)[1]       = __halves2half2(hz, hw);
        reinterpret_cast<__half2*>(base + 512)[0] = __halves2half2(lx, ly);
        reinterpret_cast<__half2*>(base + 512)[1] = __halves2half2(lz, lw);
    }
    {   // kv: fp16 hi only
        float4 a = reinterpret_cast<const float4*>(kv)[idx];
        __half* base = g_kcat + row * KK + dp;
        reinterpret_cast<__half2*>(base)[0] =
            __halves2half2(__float2half(a.x), __float2half(a.y));
        reinterpret_cast<__half2*>(base)[1] =
            __halves2half2(__float2half(a.z), __float2half(a.w));
    }
}

// ---------------- exact fp32 diagonal + zero the row-sum accumulators ----------------
__global__ void __launch_bounds__(256) diag_kernel(const float* __restrict__ q,
                                                   const float* __restrict__ kv) {
    int row  = blockIdx.x * 8 + (threadIdx.x >> 5);
    int lane = threadIdx.x & 31;
    const float* qr = q  + (size_t)row * DDIM;
    const float* kr = kv + (size_t)row * DDIM;
    float s = 0.f;
#pragma unroll
    for (int i = 0; i < 16; ++i) s += qr[lane + 32 * i] * kr[lane + 32 * i];
#pragma unroll
    for (int off = 16; off; off >>= 1) s += __shfl_xor_sync(0xffffffffu, s, off);
    if (lane == 0) {
        g_diagexp[row] = exp2f(CLOG2E * s);
        g_rsum[row] = 0.f;
    }
}

// ---------------- main GEMM + normalizer: persistent units over all SMs ----------------
__global__ void __launch_bounds__(256, 1) main_kernel(int nsm) {
    extern __shared__ char smem_raw[];
    const uint32_t st0 = (smem_u32(smem_raw) + 1023u) & ~1023u;

    const int tid  = threadIdx.x;
    const int wid  = tid >> 5;
    const int lane = tid & 31;
    const int bid  = blockIdx.x;

    // per-thread cp.async vector descriptors (16B vectors)
    int qoff[4]; uint32_t qdst[4];
#pragma unroll
    for (int i = 0; i < 4; ++i) {
        int v = tid + i * 256, r = v >> 3, j = v & 7;
        qoff[i] = r * KQ + j * 8;
        qdst[i] = sw128((uint32_t)(r * 128 + j * 16));
    }
    int koff[8]; uint32_t kdst[8];
#pragma unroll
    for (int i = 0; i < 8; ++i) {
        int v = tid + i * 256, r = v >> 3, j = v & 7;
        koff[i] = r * KK + j * 8;
        kdst[i] = sw128((uint32_t)(r * 128 + j * 16));
    }

    // unit u = nt*128 + qt : one wave shares a kv supertile (L2 reuse),
    // distinct q tiles. Each CTA strides by nsm; pipeline streams across units.
    auto issue = [&](int it) {
        const int u = bid + (it >> 3) * nsm;
        if (u >= UNITS) { cp_commit(); return; }   // empty group keeps counts uniform
        const int qt = u & (QTILES - 1), nt = u >> 7, cc = it & 7;
        const uint32_t sAh = st0 + (it % STAGES) * STB;
        const uint32_t sAl = sAh + AB;
        const uint32_t sB  = sAh + 2 * AB;
        const __half* qs = g_qcat + (size_t)qt * MT * KQ + cc * KC;
#pragma unroll
        for (int i = 0; i < 4; ++i) cp_async16(sAh + qdst[i], qs + qoff[i]);
#pragma unroll
        for (int i = 0; i < 4; ++i) cp_async16(sAl + qdst[i], qs + 512 + qoff[i]);
        const __half* ks = g_kcat +
            ((size_t)(qt >> 5) * NSEQ + (size_t)nt * NTILE) * KK + cc * KC;
#pragma unroll
        for (int i = 0; i < 8; ++i) cp_async16(sB + kdst[i], ks + koff[i]);
        cp_commit();
    };

    // warp tile: 2 M-warps x 4 N-warps, each 64x64
    const int m0 = (wid & 1) * 64;
    const int n0 = (wid >> 1) * 64;
    const int lr  = lane & 15;          // ldmatrix row within 16
    const int lcb = (lane >> 4) * 16;   // ldmatrix 16B column group

    uint32_t aBase[4], aSw[4], bBase[4], bSw[4];
#pragma unroll
    for (int f = 0; f < 4; ++f) {
        int ra = m0 + f * 16 + lr;
        aBase[f] = (uint32_t)(ra * 128); aSw[f] = (uint32_t)((ra & 7) << 4);
        int rb = n0 + f * 16 + lr;
        bBase[f] = (uint32_t)(rb * 128); bSw[f] = (uint32_t)((rb & 7) << 4);
    }

    // fp16 accumulators: hi and lo kept separate, combined in fp32 at epilogue
    uint32_t ch[4][8][2], cl[4][8][2];
#pragma unroll
    for (int mf = 0; mf < 4; ++mf)
#pragma unroll
        for (int nf = 0; nf < 8; ++nf) {
            ch[mf][nf][0] = 0u; ch[mf][nf][1] = 0u;
            cl[mf][nf][0] = 0u; cl[mf][nf][1] = 0u;
        }

    const int nunits = (UNITS - bid + nsm - 1) / nsm;   // bid < nsm <= UNITS
    const int nits   = nunits * 8;

    issue(0);
    issue(1);

    for (int it = 0; it < nits; ++it) {
        cp_wait_group<1>();
        __syncthreads();
        issue(it + 2);

        const uint32_t sAh = st0 + (it % STAGES) * STB;
        const uint32_t sAl = sAh + AB;
        const uint32_t sB  = sAh + 2 * AB;

#pragma unroll
        for (int kk = 0; kk < 4; ++kk) {
            const uint32_t cb = (uint32_t)(kk * 32) + lcb;
            uint32_t b[4][4], ah[4][4], al[4][4];
#pragma unroll
            for (int f = 0; f < 4; ++f) ldsm4(b[f],  sB  + bBase[f] + (cb ^ bSw[f]));
#pragma unroll
            for (int f = 0; f < 4; ++f) ldsm4(ah[f], sAh + aBase[f] + (cb ^ aSw[f]));
#pragma unroll
            for (int f = 0; f < 4; ++f) ldsm4(al[f], sAl + aBase[f] + (cb ^ aSw[f]));
            // hi term
#pragma unroll
            for (int mf = 0; mf < 4; ++mf)
#pragma unroll
                for (int g = 0; g < 4; ++g) {
                    mma_f16acc(ch[mf][2 * g],     ah[mf], b[g][0], b[g][2]);
                    mma_f16acc(ch[mf][2 * g + 1], ah[mf], b[g][1], b[g][3]);
                }
            // lo term (separate fp16 accumulators, same B fragments)
#pragma unroll
            for (int mf = 0; mf < 4; ++mf)
#pragma unroll
                for (int g = 0; g < 4; ++g) {
                    mma_f16acc(cl[mf][2 * g],     al[mf], b[g][0], b[g][2]);
                    mma_f16acc(cl[mf][2 * g + 1], al[mf], b[g][1], b[g][3]);
                }
        }

        if ((it & 7) == 7) {
            // unit epilogue: rowsum of 2^(hi + lo/1024) -> global accumulators
            const int qt = (bid + (it >> 3) * nsm) & (QTILES - 1);
            float* rs = g_rsum + qt * MT;
#pragma unroll
            for (int mf = 0; mf < 4; ++mf) {
                float s0 = 0.f, s1 = 0.f;
#pragma unroll
                for (int nf = 0; nf < 8; ++nf) {
                    float2 h0 = __half22float2(*reinterpret_cast<__half2*>(&ch[mf][nf][0]));
                    float2 h1 = __half22float2(*reinterpret_cast<__half2*>(&ch[mf][nf][1]));
                    float2 l0 = __half22float2(*reinterpret_cast<__half2*>(&cl[mf][nf][0]));
                    float2 l1 = __half22float2(*reinterpret_cast<__half2*>(&cl[mf][nf][1]));
                    s0 += ex2(fmaf(l0.x, LOINV, h0.x)) + ex2(fmaf(l0.y, LOINV, h0.y));
                    s1 += ex2(fmaf(l1.x, LOINV, h1.x)) + ex2(fmaf(l1.y, LOINV, h1.y));
                    ch[mf][nf][0] = 0u; ch[mf][nf][1] = 0u;
                    cl[mf][nf][0] = 0u; cl[mf][nf][1] = 0u;
                }
                s0 += __shfl_xor_sync(0xffffffffu, s0, 1);
                s0 += __shfl_xor_sync(0xffffffffu, s0, 2);
                s1 += __shfl_xor_sync(0xffffffffu, s1, 1);
                s1 += __shfl_xor_sync(0xffffffffu, s1, 2);
                if ((lane & 3) == 0) {
                    atomicAdd(&rs[m0 + mf * 16 + (lane >> 2)], s0);
                    atomicAdd(&rs[m0 + mf * 16 + 8 + (lane >> 2)], s1);
                }
            }
        }
    }
}

// ---------------- final: out = diagexp / rowsum ----------------
__global__ void __launch_bounds__(256) out_kernel(float* __restrict__ out) {
    int row = blockIdx.x * 256 + threadIdx.x;
    out[row] = g_diagexp[row] / g_rsum[row];
}

extern "C" void kernel_launch(void* const* d_in, const int* in_sizes, int n_in,
                              void* d_out, int out_size) {
    const float* q  = (const float*)d_in[0];
    const float* kv = (const float*)d_in[1];
    float* out = (float*)d_out;

    int nsm = 0;
    cudaDeviceGetAttribute(&nsm, cudaDevAttrMultiProcessorCount, 0);
    if (nsm <= 0 || nsm > UNITS) nsm = 128;

    prep_kernel<<<4096, 512>>>(q, kv);
    diag_kernel<<<2048, 256>>>(q, kv);

    cudaFuncSetAttribute(main_kernel, cudaFuncAttributeMaxDynamicSharedMemorySize,
                         SMEM_TOTAL);
    main_kernel<<<nsm, 256, SMEM_TOTAL>>>(nsm);

    out_kernel<<<BATCH * NSEQ / 256, 256>>>(out);
}